// round 7
// baseline (speedup 1.0000x reference)
#include <cuda_runtime.h>
#include <cuda_bf16.h>

// Fixed problem shapes
#define BV 4
#define DV 48
#define HV 32
#define WV 88
#define CV 64
#define NXV 200
#define NYV 200
#define HWV (HV * WV)
#define NPRIME (BV * DV * HV * WV)       // 540672 points
#define NXY (NXV * NYV)                  // 40000
#define NVOX (BV * NXY)                  // 160000 voxels (NZ=1)
#define CAP 32                           // max points binned per voxel
#define TILE 8                           // iy voxels per block (200 = 8*25)

// Per-voxel point lists. g_cnt is zero at module load; gather_kernel resets
// each counter after consuming it, so the zero-invariant holds across the
// correctness run and every graph replay.
__device__ int g_cnt[NVOX];
__device__ int g_list[NVOX * CAP];

// Pass 1: bin kept points by voxel. Only tiny spread-out atomics (270K x 4B
// increments over a 640KB L2-resident array) -- no feature atomics at all.
__global__ void bin_kernel(const float* __restrict__ geom,
                           const float* __restrict__ mask,
                           const float* __restrict__ dxp,
                           const float* __restrict__ bxp) {
    const int p = blockIdx.x * blockDim.x + threadIdx.x;
    if (p >= NPRIME) return;

    const float dx0 = dxp[0], dx1 = dxp[1], dx2 = dxp[2];
    const float b0 = bxp[0] - 0.5f * dx0;
    const float b1 = bxp[1] - 0.5f * dx1;
    const float b2 = bxp[2] - 0.5f * dx2;

    // identical op sequence to reference: sub, div, truncate toward zero
    const float gx = (geom[p * 3 + 0] - b0) / dx0;
    const float gy = (geom[p * 3 + 1] - b1) / dx1;
    const float gz = (geom[p * 3 + 2] - b2) / dx2;
    const int ix = (int)gx;
    const int iy = (int)gy;
    const int iz = (int)gz;

    const int hw = p % HWV;
    const int bn = p / (DV * HWV);       // batch (N=1)

    const bool kept =
        (ix >= 0) & (ix < NXV) &
        (iy >= 0) & (iy < NYV) &
        (iz >= 0) & (iz < 1) &
        (mask[(bn * 2 + 1) * HWV + hw] > 0.5f);

    if (kept) {
        const int v = bn * NXY + ix * NYV + iy;
        const int slot = atomicAdd(&g_cnt[v], 1);
        if (slot < CAP) g_list[v * CAP + slot] = p;
    }
}

// Pass 2: gather-accumulate per voxel in registers, transpose through smem,
// write planar output fully coalesced. Covers every output element (zeros for
// empty voxels), so no output pre-init needed. Also resets g_cnt.
__global__ void gather_kernel(const float* __restrict__ x,
                              float* __restrict__ out) {
    // block -> (b, ix, iy-tile of 8)
    const int bid = blockIdx.x;
    const int t25 = bid % 25;
    const int bi  = bid / 25;
    const int ix  = bi % NXV;
    const int b   = bi / NXV;
    const int iy0 = t25 * TILE;

    const int lane = threadIdx.x & 31;
    const int w    = threadIdx.x >> 5;          // warp 0..3
    const int half = lane >> 4;                 // half-warp: which voxel
    const int sl   = lane & 15;                 // 4-channel group
    const int vl   = 2 * w + half;              // local voxel 0..7
    const int v    = b * NXY + ix * NYV + (iy0 + vl);

    // one lane per half-warp reads & resets the counter, then broadcasts
    int n = 0;
    if (sl == 0) {
        n = g_cnt[v];
        g_cnt[v] = 0;                           // restore zero-invariant
    }
    n = __shfl_sync(0xffffffffu, n, half << 4);
    if (n > CAP) n = CAP;

    // register accumulation; software-pipelined list->x dependent loads
    float4 acc = make_float4(0.f, 0.f, 0.f, 0.f);
    int pk = (n > 0) ? g_list[v * CAP] : 0;
    for (int k = 0; k < n; k++) {
        const int pn = (k + 1 < n) ? g_list[v * CAP + k + 1] : 0;
        const float4 vv = *reinterpret_cast<const float4*>(
            x + (size_t)pk * CV + 4 * sl);      // 16 lanes -> 256B coalesced
        acc.x += vv.x; acc.y += vv.y; acc.z += vv.z; acc.w += vv.w;
        pk = pn;
    }

    // transpose (voxel, chgroup) -> (channel, iy) through smem
    __shared__ float4 sm[TILE][17];             // padded: conflict-free
    sm[vl][sl] = acc;
    __syncthreads();

    const float* s = reinterpret_cast<const float*>(sm);  // row stride 68
    const int t = threadIdx.x;
    const int c = t >> 1;                       // channel 0..63
    const int q = t & 1;                        // iy quad 0..1
    float4 o4;
    o4.x = s[(4 * q + 0) * 68 + c];
    o4.y = s[(4 * q + 1) * 68 + c];
    o4.z = s[(4 * q + 2) * 68 + c];
    o4.w = s[(4 * q + 3) * 68 + c];
    *reinterpret_cast<float4*>(
        out + (size_t)(b * CV + c) * NXY + ix * NYV + iy0 + 4 * q) = o4;
}

extern "C" void kernel_launch(void* const* d_in, const int* in_sizes, int n_in,
                              void* d_out, int out_size) {
    const float* x    = (const float*)d_in[0];
    const float* geom = (const float*)d_in[1];
    const float* mask = (const float*)d_in[2];
    const float* dx   = (const float*)d_in[3];
    const float* bx   = (const float*)d_in[4];
    float* out = (float*)d_out;

    // 1) bin points by voxel (counters start at zero; gather resets them)
    bin_kernel<<<NPRIME / 256, 256>>>(geom, mask, dx, bx);

    // 2) gather-accumulate in registers + coalesced planar write
    gather_kernel<<<BV * NXV * 25, 128>>>(x, out);
}